// round 3
// baseline (speedup 1.0000x reference)
#include <cuda_runtime.h>

#define NN 50000
#define DD 128
#define BN_EPS 1e-5f

// ---- scratch (device globals: allocation-free per harness rules) ----
__device__ float g_xw[NN * DD];      // x @ W
__device__ float g_agg[NN * DD];     // aggregated messages (init = self-loop term)
__device__ float g_deg[NN];
__device__ float g_dinv[NN];
__device__ float g_colsum[DD];
__device__ float g_colsumsq[DD];
__device__ float g_mean[DD];
__device__ float g_scale[DD];        // gamma * rsqrt(var+eps)
__device__ int   g_is64;             // 1 if edge_index is int64, 0 if int32

// ---- K0: detect edge_index dtype from content (deterministic) ----
__global__ void k_detect(const void* __restrict__ ei, int N) {
    if (blockIdx.x == 0 && threadIdx.x == 0) {
        const long long* p64 = (const long long*)ei;
        int bad = 0;
        for (int i = 0; i < 256; i++) {
            long long v = p64[i];
            if (v < 0 || v >= N) bad++;
        }
        g_is64 = (bad == 0) ? 1 : 0;
    }
}

__device__ __forceinline__ int edge_at(const void* ei, int idx) {
    return g_is64 ? (int)((const long long*)ei)[idx]
                  : ((const int*)ei)[idx];
}

// ---- K1: init degrees (self loop = 1) + zero BN accumulators ----
__global__ void k_init(int N) {
    int i = blockIdx.x * blockDim.x + threadIdx.x;
    if (i < N) g_deg[i] = 1.0f;
    if (i < DD) { g_colsum[i] = 0.0f; g_colsumsq[i] = 0.0f; }
}

// ---- K2: degree accumulation on row index ----
__global__ void k_deg(const void* __restrict__ ei, int E, int N) {
    int e = blockIdx.x * blockDim.x + threadIdx.x;
    if (e >= E) return;
    int row = edge_at(ei, e);
    if ((unsigned)row < (unsigned)N) atomicAdd(&g_deg[row], 1.0f);
}

// ---- K3: dinv = deg^-0.5 (deg >= 1 always, self loops) ----
__global__ void k_dinv(int N) {
    int i = blockIdx.x * blockDim.x + threadIdx.x;
    if (i < N) g_dinv[i] = rsqrtf(g_deg[i]);
}

// ---- K4: xw = x @ W, and agg initialized with self-loop term xw*dinv^2 ----
// Warp computes 8 rows x 128 cols: each lane owns 4 consecutive cols (float4).
// W (64KB) is read via LDG and stays L1-resident; x rows stream.
__global__ __launch_bounds__(256) void k_gemm(const float* __restrict__ x,
                                              const float* __restrict__ W,
                                              int N) {
    int lane = threadIdx.x & 31;
    int gw = (blockIdx.x * blockDim.x + threadIdx.x) >> 5;
    int r0 = gw * 8;
    if (r0 >= N) return;
    int rows = min(8, N - r0);

    const float4* W4 = (const float4*)W;
    const float4* x4 = (const float4*)x;

    float4 acc[8];
#pragma unroll
    for (int r = 0; r < 8; r++) acc[r] = make_float4(0.f, 0.f, 0.f, 0.f);

#pragma unroll 4
    for (int k4 = 0; k4 < 32; k4++) {
        float4 wv0 = W4[(k4 * 4 + 0) * 32 + lane];
        float4 wv1 = W4[(k4 * 4 + 1) * 32 + lane];
        float4 wv2 = W4[(k4 * 4 + 2) * 32 + lane];
        float4 wv3 = W4[(k4 * 4 + 3) * 32 + lane];
#pragma unroll
        for (int r = 0; r < 8; r++) {
            int row = r0 + r; if (row >= N) row = N - 1;   // clamp
            float4 xv = x4[row * 32 + k4];                 // broadcast across warp
            acc[r].x = fmaf(xv.x, wv0.x, acc[r].x);
            acc[r].y = fmaf(xv.x, wv0.y, acc[r].y);
            acc[r].z = fmaf(xv.x, wv0.z, acc[r].z);
            acc[r].w = fmaf(xv.x, wv0.w, acc[r].w);
            acc[r].x = fmaf(xv.y, wv1.x, acc[r].x);
            acc[r].y = fmaf(xv.y, wv1.y, acc[r].y);
            acc[r].z = fmaf(xv.y, wv1.z, acc[r].z);
            acc[r].w = fmaf(xv.y, wv1.w, acc[r].w);
            acc[r].x = fmaf(xv.z, wv2.x, acc[r].x);
            acc[r].y = fmaf(xv.z, wv2.y, acc[r].y);
            acc[r].z = fmaf(xv.z, wv2.z, acc[r].z);
            acc[r].w = fmaf(xv.z, wv2.w, acc[r].w);
            acc[r].x = fmaf(xv.w, wv3.x, acc[r].x);
            acc[r].y = fmaf(xv.w, wv3.y, acc[r].y);
            acc[r].z = fmaf(xv.w, wv3.z, acc[r].z);
            acc[r].w = fmaf(xv.w, wv3.w, acc[r].w);
        }
    }

    float4* xw4 = (float4*)g_xw;
    float4* ag4 = (float4*)g_agg;
#pragma unroll
    for (int r = 0; r < 8; r++) {
        if (r < rows) {
            int row = r0 + r;
            float di = g_dinv[row];
            float s = di * di;                 // self-loop norm
            xw4[row * 32 + lane] = acc[r];
            float4 ag = make_float4(acc[r].x * s, acc[r].y * s,
                                    acc[r].z * s, acc[r].w * s);
            ag4[row * 32 + lane] = ag;
        }
    }
}

// ---- K5: scatter-add messages. One warp per edge (grid-stride). ----
// gather xw[col] (L2-resident), scale by dinv[row]*dinv[col],
// scalar atomicAdd (RED.E.ADD.F32, return unused) into agg[row].
__global__ __launch_bounds__(256) void k_scatter(const void* __restrict__ ei,
                                                 int E, int N) {
    int lane = threadIdx.x & 31;
    int gw = (blockIdx.x * blockDim.x + threadIdx.x) >> 5;
    int nw = (gridDim.x * blockDim.x) >> 5;
    const float4* xw4 = (const float4*)g_xw;
    for (int e = gw; e < E; e += nw) {
        int row = edge_at(ei, e);
        int col = edge_at(ei, E + e);
        if ((unsigned)row >= (unsigned)N || (unsigned)col >= (unsigned)N) continue;
        float nrm = g_dinv[row] * g_dinv[col];
        float4 v = xw4[col * 32 + lane];
        float* p = g_agg + row * DD + lane * 4;
        atomicAdd(p + 0, v.x * nrm);
        atomicAdd(p + 1, v.y * nrm);
        atomicAdd(p + 2, v.z * nrm);
        atomicAdd(p + 3, v.w * nrm);
    }
}

// ---- K6: BN column statistics (sum, sumsq). 128 threads = 128 columns. ----
__global__ void k_bnstats(int N) {
    int c = threadIdx.x;
    float s = 0.f, s2 = 0.f;
    for (int r = blockIdx.x; r < N; r += gridDim.x) {
        float v = g_agg[r * DD + c];
        s += v;
        s2 = fmaf(v, v, s2);
    }
    atomicAdd(&g_colsum[c], s);
    atomicAdd(&g_colsumsq[c], s2);
}

// ---- K7: finalize BN params (bias b cancels through mean subtraction) ----
__global__ void k_bnparam(const float* __restrict__ gamma, float nInv) {
    int c = threadIdx.x;
    float mean = g_colsum[c] * nInv;
    float var = g_colsumsq[c] * nInv - mean * mean;
    g_mean[c] = mean;
    g_scale[c] = rsqrtf(var + BN_EPS) * gamma[c];
}

// ---- K8: y = relu((agg - mean)*scale + beta) + x ----
__global__ void k_final(const float* __restrict__ x, const float* __restrict__ beta,
                        float* __restrict__ out, int n4) {
    int t = blockIdx.x * blockDim.x + threadIdx.x;
    if (t >= n4) return;
    int cb = t & 31;  // float4-column index
    float4 a  = ((const float4*)g_agg)[t];
    float4 xr = ((const float4*)x)[t];
    float4 m  = ((const float4*)g_mean)[cb];
    float4 s  = ((const float4*)g_scale)[cb];
    float4 bt = ((const float4*)beta)[cb];
    float4 r;
    r.x = fmaxf((a.x - m.x) * s.x + bt.x, 0.f) + xr.x;
    r.y = fmaxf((a.y - m.y) * s.y + bt.y, 0.f) + xr.y;
    r.z = fmaxf((a.z - m.z) * s.z + bt.z, 0.f) + xr.z;
    r.w = fmaxf((a.w - m.w) * s.w + bt.w, 0.f) + xr.w;
    ((float4*)out)[t] = r;
}

extern "C" void kernel_launch(void* const* d_in, const int* in_sizes, int n_in,
                              void* d_out, int out_size) {
    const float* x     = (const float*)d_in[0];
    const void*  ei    = d_in[1];                 // int32 or int64, detected on device
    const float* W     = (const float*)d_in[2];
    // d_in[3] = b — cancels exactly through BatchNorm, unused
    const float* gamma = (const float*)d_in[4];
    const float* beta  = (const float*)d_in[5];
    float*       out   = (float*)d_out;

    int N = in_sizes[0] / DD;
    int E = in_sizes[1] / 2;

    k_detect<<<1, 32>>>(ei, N);
    k_init<<<(N + 255) / 256, 256>>>(N);
    k_deg<<<(E + 255) / 256, 256>>>(ei, E, N);
    k_dinv<<<(N + 255) / 256, 256>>>(N);

    int gwarps = (N + 7) / 8;
    int gblocks = (gwarps + 7) / 8;
    k_gemm<<<gblocks, 256>>>(x, W, N);

    k_scatter<<<2048, 256>>>(ei, E, N);

    k_bnstats<<<512, 128>>>(N);
    k_bnparam<<<1, DD>>>(gamma, 1.0f / (float)N);

    int n4 = N * (DD / 4);
    k_final<<<(n4 + 255) / 256, 256>>>(x, beta, out, n4);
}

// round 4
// speedup vs baseline: 1.8650x; 1.8650x over previous
#include <cuda_runtime.h>

#define NN 50000
#define EE 800000
#define DD 128
#define BN_EPS 1e-5f

// ---- scratch (device globals: allocation-free per harness rules) ----
__device__ float g_xw[NN * DD];      // x @ W
__device__ float g_agg[NN * DD];     // aggregated output of GCN conv
__device__ float g_dinv[NN];
__device__ int   g_degi[NN];
__device__ int   g_off[NN + 1];      // CSR offsets
__device__ int   g_cur[NN];          // fill cursors
__device__ int   g_rowi[EE];         // edge rows as int32
__device__ int   g_coli[EE];         // edge cols as int32
__device__ int   g_adj[EE];          // CSR adjacency (col indices)
__device__ float g_colsum[DD];
__device__ float g_colsumsq[DD];
__device__ float g_mean[DD];
__device__ float g_scale[DD];        // gamma * rsqrt(var+eps)
__device__ int   g_is64;             // 1 if edge_index is int64, 0 if int32

// ---- K0: detect edge_index dtype from content (deterministic) ----
__global__ void k_detect(const void* __restrict__ ei, int N) {
    if (threadIdx.x == 0) {
        const long long* p64 = (const long long*)ei;
        int bad = 0;
        for (int i = 0; i < 256; i++) {
            long long v = p64[i];
            if (v < 0 || v >= N) bad++;
        }
        g_is64 = (bad == 0) ? 1 : 0;
    }
}

// ---- K1: zero int degrees + BN accumulators ----
__global__ void k_init(int N) {
    int i = blockIdx.x * blockDim.x + threadIdx.x;
    if (i < N) g_degi[i] = 0;
    if (i < DD) { g_colsum[i] = 0.0f; g_colsumsq[i] = 0.0f; }
}

// ---- K2: convert edges to int32 + histogram rows ----
__global__ void k_prep(const void* __restrict__ ei, int E, int N) {
    int e = blockIdx.x * blockDim.x + threadIdx.x;
    if (e >= E) return;
    int row, col;
    if (g_is64) {
        row = (int)((const long long*)ei)[e];
        col = (int)((const long long*)ei)[E + e];
    } else {
        row = ((const int*)ei)[e];
        col = ((const int*)ei)[E + e];
    }
    if ((unsigned)row >= (unsigned)N || (unsigned)col >= (unsigned)N) {
        g_rowi[e] = -1; g_coli[e] = 0;
        return;
    }
    g_rowi[e] = row;
    g_coli[e] = col;
    atomicAdd(&g_degi[row], 1);
}

// ---- K3: exclusive scan of degrees -> CSR offsets (single block, shuffle scan) ----
__global__ __launch_bounds__(1024) void k_scan(int N) {
    __shared__ int warp_tot[32];
    __shared__ int carry_s;
    int tid = threadIdx.x;
    int lane = tid & 31, wid = tid >> 5;
    if (tid == 0) { carry_s = 0; g_off[0] = 0; }
    __syncthreads();
    for (int base = 0; base < N; base += 1024) {
        int i = base + tid;
        int v = (i < N) ? g_degi[i] : 0;
        int s = v;
#pragma unroll
        for (int d = 1; d < 32; d <<= 1) {
            int t = __shfl_up_sync(0xffffffffu, s, d);
            if (lane >= d) s += t;
        }
        if (lane == 31) warp_tot[wid] = s;
        __syncthreads();
        if (wid == 0) {
            int t = warp_tot[lane];
            int ws = t;
#pragma unroll
            for (int d = 1; d < 32; d <<= 1) {
                int u = __shfl_up_sync(0xffffffffu, ws, d);
                if (lane >= d) ws += u;
            }
            warp_tot[lane] = ws - t;  // exclusive warp offsets
        }
        __syncthreads();
        int incl = s + warp_tot[wid] + carry_s;
        if (i < N) g_off[i + 1] = incl;
        __syncthreads();
        if (tid == 1023) carry_s = incl;
        __syncthreads();
    }
}

// ---- K4: dinv = (deg+1)^-0.5, init fill cursors ----
__global__ void k_dinv(int N) {
    int i = blockIdx.x * blockDim.x + threadIdx.x;
    if (i < N) {
        g_dinv[i] = rsqrtf((float)(g_degi[i] + 1));
        g_cur[i] = g_off[i];
    }
}

// ---- K5: CSR fill ----
__global__ void k_fill(int E) {
    int e = blockIdx.x * blockDim.x + threadIdx.x;
    if (e >= E) return;
    int row = g_rowi[e];
    if (row < 0) return;
    int pos = atomicAdd(&g_cur[row], 1);
    g_adj[pos] = g_coli[e];
}

// ---- K6: xw = x @ W (warp = 8 rows x 128 cols; W L1-resident) ----
__global__ __launch_bounds__(256) void k_gemm(const float* __restrict__ x,
                                              const float* __restrict__ W,
                                              int N) {
    int lane = threadIdx.x & 31;
    int gw = (blockIdx.x * blockDim.x + threadIdx.x) >> 5;
    int r0 = gw * 8;
    if (r0 >= N) return;
    int rows = min(8, N - r0);

    const float4* W4 = (const float4*)W;
    const float4* x4 = (const float4*)x;

    float4 acc[8];
#pragma unroll
    for (int r = 0; r < 8; r++) acc[r] = make_float4(0.f, 0.f, 0.f, 0.f);

#pragma unroll 4
    for (int k4 = 0; k4 < 32; k4++) {
        float4 wv0 = W4[(k4 * 4 + 0) * 32 + lane];
        float4 wv1 = W4[(k4 * 4 + 1) * 32 + lane];
        float4 wv2 = W4[(k4 * 4 + 2) * 32 + lane];
        float4 wv3 = W4[(k4 * 4 + 3) * 32 + lane];
#pragma unroll
        for (int r = 0; r < 8; r++) {
            int row = r0 + r; if (row >= N) row = N - 1;
            float4 xv = x4[row * 32 + k4];
            acc[r].x = fmaf(xv.x, wv0.x, acc[r].x);
            acc[r].y = fmaf(xv.x, wv0.y, acc[r].y);
            acc[r].z = fmaf(xv.x, wv0.z, acc[r].z);
            acc[r].w = fmaf(xv.x, wv0.w, acc[r].w);
            acc[r].x = fmaf(xv.y, wv1.x, acc[r].x);
            acc[r].y = fmaf(xv.y, wv1.y, acc[r].y);
            acc[r].z = fmaf(xv.y, wv1.z, acc[r].z);
            acc[r].w = fmaf(xv.y, wv1.w, acc[r].w);
            acc[r].x = fmaf(xv.z, wv2.x, acc[r].x);
            acc[r].y = fmaf(xv.z, wv2.y, acc[r].y);
            acc[r].z = fmaf(xv.z, wv2.z, acc[r].z);
            acc[r].w = fmaf(xv.z, wv2.w, acc[r].w);
            acc[r].x = fmaf(xv.w, wv3.x, acc[r].x);
            acc[r].y = fmaf(xv.w, wv3.y, acc[r].y);
            acc[r].z = fmaf(xv.w, wv3.z, acc[r].z);
            acc[r].w = fmaf(xv.w, wv3.w, acc[r].w);
        }
    }

    float4* xw4 = (float4*)g_xw;
#pragma unroll
    for (int r = 0; r < 8; r++)
        if (r < rows) xw4[(r0 + r) * 32 + lane] = acc[r];
}

// ---- K7: per-node gather (NO atomics). warp = 1 node. ----
// agg[n] = dinv[n] * ( xw[n]*dinv[n] + sum_{c in adj(n)} dinv[c]*xw[c] )
__global__ __launch_bounds__(256) void k_gather(int N) {
    int lane = threadIdx.x & 31;
    int n = (blockIdx.x * blockDim.x + threadIdx.x) >> 5;
    if (n >= N) return;
    int j = g_off[n], end = g_off[n + 1];
    const float4* xw4 = (const float4*)g_xw;

    float4 acc = make_float4(0.f, 0.f, 0.f, 0.f);
    for (; j + 2 <= end; j += 2) {                // unroll-2 for MLP
        int c0 = g_adj[j], c1 = g_adj[j + 1];
        float w0 = g_dinv[c0], w1 = g_dinv[c1];
        float4 v0 = xw4[c0 * 32 + lane];
        float4 v1 = xw4[c1 * 32 + lane];
        acc.x += v0.x * w0 + v1.x * w1;
        acc.y += v0.y * w0 + v1.y * w1;
        acc.z += v0.z * w0 + v1.z * w1;
        acc.w += v0.w * w0 + v1.w * w1;
    }
    if (j < end) {
        int c0 = g_adj[j];
        float w0 = g_dinv[c0];
        float4 v0 = xw4[c0 * 32 + lane];
        acc.x += v0.x * w0; acc.y += v0.y * w0;
        acc.z += v0.z * w0; acc.w += v0.w * w0;
    }
    float dr = g_dinv[n];
    float4 sv = xw4[n * 32 + lane];
    acc.x = (acc.x + sv.x * dr) * dr;
    acc.y = (acc.y + sv.y * dr) * dr;
    acc.z = (acc.z + sv.z * dr) * dr;
    acc.w = (acc.w + sv.w * dr) * dr;
    ((float4*)g_agg)[n * 32 + lane] = acc;
}

// ---- K8: BN column statistics ----
__global__ void k_bnstats(int N) {
    int c = threadIdx.x;
    float s = 0.f, s2 = 0.f;
    for (int r = blockIdx.x; r < N; r += gridDim.x) {
        float v = g_agg[r * DD + c];
        s += v;
        s2 = fmaf(v, v, s2);
    }
    atomicAdd(&g_colsum[c], s);
    atomicAdd(&g_colsumsq[c], s2);
}

// ---- K9: finalize BN params (bias b cancels through mean subtraction) ----
__global__ void k_bnparam(const float* __restrict__ gamma, float nInv) {
    int c = threadIdx.x;
    float mean = g_colsum[c] * nInv;
    float var = g_colsumsq[c] * nInv - mean * mean;
    g_mean[c] = mean;
    g_scale[c] = rsqrtf(var + BN_EPS) * gamma[c];
}

// ---- K10: y = relu((agg - mean)*scale + beta) + x ----
__global__ void k_final(const float* __restrict__ x, const float* __restrict__ beta,
                        float* __restrict__ out, int n4) {
    int t = blockIdx.x * blockDim.x + threadIdx.x;
    if (t >= n4) return;
    int cb = t & 31;
    float4 a  = ((const float4*)g_agg)[t];
    float4 xr = ((const float4*)x)[t];
    float4 m  = ((const float4*)g_mean)[cb];
    float4 s  = ((const float4*)g_scale)[cb];
    float4 bt = ((const float4*)beta)[cb];
    float4 r;
    r.x = fmaxf((a.x - m.x) * s.x + bt.x, 0.f) + xr.x;
    r.y = fmaxf((a.y - m.y) * s.y + bt.y, 0.f) + xr.y;
    r.z = fmaxf((a.z - m.z) * s.z + bt.z, 0.f) + xr.z;
    r.w = fmaxf((a.w - m.w) * s.w + bt.w, 0.f) + xr.w;
    ((float4*)out)[t] = r;
}

extern "C" void kernel_launch(void* const* d_in, const int* in_sizes, int n_in,
                              void* d_out, int out_size) {
    const float* x     = (const float*)d_in[0];
    const void*  ei    = d_in[1];                 // int32 or int64, detected on device
    const float* W     = (const float*)d_in[2];
    // d_in[3] = b — cancels exactly through BatchNorm, unused
    const float* gamma = (const float*)d_in[4];
    const float* beta  = (const float*)d_in[5];
    float*       out   = (float*)d_out;

    int N = in_sizes[0] / DD;
    int E = in_sizes[1] / 2;

    k_detect<<<1, 32>>>(ei, N);
    k_init<<<(N + 255) / 256, 256>>>(N);
    k_prep<<<(E + 255) / 256, 256>>>(ei, E, N);
    k_scan<<<1, 1024>>>(N);
    k_dinv<<<(N + 255) / 256, 256>>>(N);
    k_fill<<<(E + 255) / 256, 256>>>(E);

    int gwarps = (N + 7) / 8;
    k_gemm<<<(gwarps + 7) / 8, 256>>>(x, W, N);

    k_gather<<<(N + 7) / 8, 256>>>(N);

    k_bnstats<<<512, 128>>>(N);
    k_bnparam<<<1, DD>>>(gamma, 1.0f / (float)N);

    int n4 = N * (DD / 4);
    k_final<<<(n4 + 255) / 256, 256>>>(x, beta, out, n4);
}

// round 5
// speedup vs baseline: 2.2025x; 1.1809x over previous
#include <cuda_runtime.h>

#define NN 50000
#define EE 800000
#define DD 128
#define BN_EPS 1e-5f
#define SCAN_B 1024
#define NBLK ((NN + SCAN_B - 1) / SCAN_B)   // 49

// ---- scratch (device globals: allocation-free per harness rules) ----
__device__ float g_xw[NN * DD];      // x @ W
__device__ float g_agg[NN * DD];     // aggregated output of GCN conv
__device__ float g_dinv[NN];
__device__ int   g_degi[NN];
__device__ int   g_off[NN + 1];      // CSR offsets
__device__ int   g_cur[NN];          // fill cursors
__device__ int   g_rowi[EE];         // edge rows as int32
__device__ int   g_coli[EE];         // edge cols as int32
__device__ int   g_adj[EE];          // CSR adjacency (col indices)
__device__ int   g_bsum[NBLK];       // per-block scan totals
__device__ int   g_boff[NBLK];       // exclusive block offsets
__device__ float g_colsum[DD];
__device__ float g_colsumsq[DD];
__device__ float g_mean[DD];
__device__ float g_scale[DD];        // gamma * rsqrt(var+eps)
__device__ int   g_is64;             // 1 if edge_index is int64, 0 if int32

// ---- K0: detect edge_index dtype from content (deterministic) ----
__global__ void k_detect(const void* __restrict__ ei, int N) {
    if (threadIdx.x == 0) {
        const long long* p64 = (const long long*)ei;
        int bad = 0;
        for (int i = 0; i < 256; i++) {
            long long v = p64[i];
            if (v < 0 || v >= N) bad++;
        }
        g_is64 = (bad == 0) ? 1 : 0;
    }
}

// ---- K1: zero int degrees + BN accumulators ----
__global__ void k_init(int N) {
    int i = blockIdx.x * blockDim.x + threadIdx.x;
    if (i < N) g_degi[i] = 0;
    if (i < DD) { g_colsum[i] = 0.0f; g_colsumsq[i] = 0.0f; }
}

// ---- K2: convert edges to int32 + histogram rows ----
__global__ void k_prep(const void* __restrict__ ei, int E, int N) {
    int e = blockIdx.x * blockDim.x + threadIdx.x;
    if (e >= E) return;
    int row, col;
    if (g_is64) {
        row = (int)((const long long*)ei)[e];
        col = (int)((const long long*)ei)[E + e];
    } else {
        row = ((const int*)ei)[e];
        col = ((const int*)ei)[E + e];
    }
    if ((unsigned)row >= (unsigned)N || (unsigned)col >= (unsigned)N) {
        g_rowi[e] = -1; g_coli[e] = 0;
        return;
    }
    g_rowi[e] = row;
    g_coli[e] = col;
    atomicAdd(&g_degi[row], 1);
}

// ---- K3a: per-block inclusive scan + block totals ----
__global__ __launch_bounds__(SCAN_B) void k_scan1(int N) {
    __shared__ int warp_tot[32];
    int tid = threadIdx.x;
    int lane = tid & 31, wid = tid >> 5;
    int i = blockIdx.x * SCAN_B + tid;
    int v = (i < N) ? g_degi[i] : 0;
    int s = v;
#pragma unroll
    for (int d = 1; d < 32; d <<= 1) {
        int t = __shfl_up_sync(0xffffffffu, s, d);
        if (lane >= d) s += t;
    }
    if (lane == 31) warp_tot[wid] = s;
    __syncthreads();
    if (wid == 0) {
        int t = warp_tot[lane];
        int ws = t;
#pragma unroll
        for (int d = 1; d < 32; d <<= 1) {
            int u = __shfl_up_sync(0xffffffffu, ws, d);
            if (lane >= d) ws += u;
        }
        warp_tot[lane] = ws - t;  // exclusive warp offsets
    }
    __syncthreads();
    int incl = s + warp_tot[wid];
    if (i < N) g_off[i + 1] = incl;          // block-local inclusive
    if (tid == SCAN_B - 1) g_bsum[blockIdx.x] = incl;
}

// ---- K3b: exclusive scan of block totals (NBLK <= 64) ----
__global__ void k_scan2(int nblk) {
    int lane = threadIdx.x;               // 64 threads, 2 warps
    __shared__ int w0_tot;
    int v = (lane < nblk) ? g_bsum[lane] : 0;
    int s = v;
    int l = lane & 31;
#pragma unroll
    for (int d = 1; d < 32; d <<= 1) {
        int t = __shfl_up_sync(0xffffffffu, s, d);
        if (l >= d) s += t;
    }
    if (lane == 31) w0_tot = s;
    __syncthreads();
    int excl = s - v + ((lane >= 32) ? w0_tot : 0);
    if (lane < nblk) g_boff[lane] = excl;
    if (lane == 0) g_off[0] = 0;
}

// ---- K3c: add block offsets ----
__global__ __launch_bounds__(SCAN_B) void k_scan3(int N) {
    int i = blockIdx.x * SCAN_B + threadIdx.x;
    if (i < N && blockIdx.x > 0) g_off[i + 1] += g_boff[blockIdx.x];
}

// ---- K4: dinv = (deg+1)^-0.5, init fill cursors ----
__global__ void k_dinv(int N) {
    int i = blockIdx.x * blockDim.x + threadIdx.x;
    if (i < N) {
        g_dinv[i] = rsqrtf((float)(g_degi[i] + 1));
        g_cur[i] = g_off[i];
    }
}

// ---- K5: CSR fill ----
__global__ void k_fill(int E) {
    int e = blockIdx.x * blockDim.x + threadIdx.x;
    if (e >= E) return;
    int row = g_rowi[e];
    if (row < 0) return;
    int pos = atomicAdd(&g_cur[row], 1);
    g_adj[pos] = g_coli[e];
}

// ---- K6: xw = x @ W (warp = 8 rows x 128 cols; W L1-resident) ----
__global__ __launch_bounds__(256) void k_gemm(const float* __restrict__ x,
                                              const float* __restrict__ W,
                                              int N) {
    int lane = threadIdx.x & 31;
    int gw = (blockIdx.x * blockDim.x + threadIdx.x) >> 5;
    int r0 = gw * 8;
    if (r0 >= N) return;
    int rows = min(8, N - r0);

    const float4* W4 = (const float4*)W;
    const float4* x4 = (const float4*)x;

    float4 acc[8];
#pragma unroll
    for (int r = 0; r < 8; r++) acc[r] = make_float4(0.f, 0.f, 0.f, 0.f);

#pragma unroll 4
    for (int k4 = 0; k4 < 32; k4++) {
        float4 wv0 = W4[(k4 * 4 + 0) * 32 + lane];
        float4 wv1 = W4[(k4 * 4 + 1) * 32 + lane];
        float4 wv2 = W4[(k4 * 4 + 2) * 32 + lane];
        float4 wv3 = W4[(k4 * 4 + 3) * 32 + lane];
#pragma unroll
        for (int r = 0; r < 8; r++) {
            int row = r0 + r; if (row >= N) row = N - 1;
            float4 xv = x4[row * 32 + k4];
            acc[r].x = fmaf(xv.x, wv0.x, acc[r].x);
            acc[r].y = fmaf(xv.x, wv0.y, acc[r].y);
            acc[r].z = fmaf(xv.x, wv0.z, acc[r].z);
            acc[r].w = fmaf(xv.x, wv0.w, acc[r].w);
            acc[r].x = fmaf(xv.y, wv1.x, acc[r].x);
            acc[r].y = fmaf(xv.y, wv1.y, acc[r].y);
            acc[r].z = fmaf(xv.y, wv1.z, acc[r].z);
            acc[r].w = fmaf(xv.y, wv1.w, acc[r].w);
            acc[r].x = fmaf(xv.z, wv2.x, acc[r].x);
            acc[r].y = fmaf(xv.z, wv2.y, acc[r].y);
            acc[r].z = fmaf(xv.z, wv2.z, acc[r].z);
            acc[r].w = fmaf(xv.z, wv2.w, acc[r].w);
            acc[r].x = fmaf(xv.w, wv3.x, acc[r].x);
            acc[r].y = fmaf(xv.w, wv3.y, acc[r].y);
            acc[r].z = fmaf(xv.w, wv3.z, acc[r].z);
            acc[r].w = fmaf(xv.w, wv3.w, acc[r].w);
        }
    }

    float4* xw4 = (float4*)g_xw;
#pragma unroll
    for (int r = 0; r < 8; r++)
        if (r < rows) xw4[(r0 + r) * 32 + lane] = acc[r];
}

// ---- K7: per-node gather (NO atomics). warp = 1 node. ----
// agg[n] = dinv[n] * ( xw[n]*dinv[n] + sum_{c in adj(n)} dinv[c]*xw[c] )
__global__ __launch_bounds__(256) void k_gather(int N) {
    int lane = threadIdx.x & 31;
    int n = (blockIdx.x * blockDim.x + threadIdx.x) >> 5;
    if (n >= N) return;
    int j = g_off[n], end = g_off[n + 1];
    const float4* xw4 = (const float4*)g_xw;

    float4 acc = make_float4(0.f, 0.f, 0.f, 0.f);
    for (; j + 2 <= end; j += 2) {                // unroll-2 for MLP
        int c0 = g_adj[j], c1 = g_adj[j + 1];
        float w0 = g_dinv[c0], w1 = g_dinv[c1];
        float4 v0 = xw4[c0 * 32 + lane];
        float4 v1 = xw4[c1 * 32 + lane];
        acc.x += v0.x * w0 + v1.x * w1;
        acc.y += v0.y * w0 + v1.y * w1;
        acc.z += v0.z * w0 + v1.z * w1;
        acc.w += v0.w * w0 + v1.w * w1;
    }
    if (j < end) {
        int c0 = g_adj[j];
        float w0 = g_dinv[c0];
        float4 v0 = xw4[c0 * 32 + lane];
        acc.x += v0.x * w0; acc.y += v0.y * w0;
        acc.z += v0.z * w0; acc.w += v0.w * w0;
    }
    float dr = g_dinv[n];
    float4 sv = xw4[n * 32 + lane];
    acc.x = (acc.x + sv.x * dr) * dr;
    acc.y = (acc.y + sv.y * dr) * dr;
    acc.z = (acc.z + sv.z * dr) * dr;
    acc.w = (acc.w + sv.w * dr) * dr;
    ((float4*)g_agg)[n * 32 + lane] = acc;
}

// ---- K8: BN column statistics ----
__global__ void k_bnstats(int N) {
    int c = threadIdx.x;
    float s = 0.f, s2 = 0.f;
    for (int r = blockIdx.x; r < N; r += gridDim.x) {
        float v = g_agg[r * DD + c];
        s += v;
        s2 = fmaf(v, v, s2);
    }
    atomicAdd(&g_colsum[c], s);
    atomicAdd(&g_colsumsq[c], s2);
}

// ---- K9: finalize BN params (bias b cancels through mean subtraction) ----
__global__ void k_bnparam(const float* __restrict__ gamma, float nInv) {
    int c = threadIdx.x;
    float mean = g_colsum[c] * nInv;
    float var = g_colsumsq[c] * nInv - mean * mean;
    g_mean[c] = mean;
    g_scale[c] = rsqrtf(var + BN_EPS) * gamma[c];
}

// ---- K10: y = relu((agg - mean)*scale + beta) + x ----
__global__ void k_final(const float* __restrict__ x, const float* __restrict__ beta,
                        float* __restrict__ out, int n4) {
    int t = blockIdx.x * blockDim.x + threadIdx.x;
    if (t >= n4) return;
    int cb = t & 31;
    float4 a  = ((const float4*)g_agg)[t];
    float4 xr = ((const float4*)x)[t];
    float4 m  = ((const float4*)g_mean)[cb];
    float4 s  = ((const float4*)g_scale)[cb];
    float4 bt = ((const float4*)beta)[cb];
    float4 r;
    r.x = fmaxf((a.x - m.x) * s.x + bt.x, 0.f) + xr.x;
    r.y = fmaxf((a.y - m.y) * s.y + bt.y, 0.f) + xr.y;
    r.z = fmaxf((a.z - m.z) * s.z + bt.z, 0.f) + xr.z;
    r.w = fmaxf((a.w - m.w) * s.w + bt.w, 0.f) + xr.w;
    ((float4*)out)[t] = r;
}

extern "C" void kernel_launch(void* const* d_in, const int* in_sizes, int n_in,
                              void* d_out, int out_size) {
    const float* x     = (const float*)d_in[0];
    const void*  ei    = d_in[1];                 // int32 or int64, detected on device
    const float* W     = (const float*)d_in[2];
    // d_in[3] = b — cancels exactly through BatchNorm, unused
    const float* gamma = (const float*)d_in[4];
    const float* beta  = (const float*)d_in[5];
    float*       out   = (float*)d_out;

    int N = in_sizes[0] / DD;
    int E = in_sizes[1] / 2;
    int nblk = (N + SCAN_B - 1) / SCAN_B;

    k_detect<<<1, 32>>>(ei, N);
    k_init<<<(N + 255) / 256, 256>>>(N);
    k_prep<<<(E + 255) / 256, 256>>>(ei, E, N);
    k_scan1<<<nblk, SCAN_B>>>(N);
    k_scan2<<<1, 64>>>(nblk);
    k_scan3<<<nblk, SCAN_B>>>(N);
    k_dinv<<<(N + 255) / 256, 256>>>(N);
    k_fill<<<(E + 255) / 256, 256>>>(E);

    int gwarps = (N + 7) / 8;
    k_gemm<<<(gwarps + 7) / 8, 256>>>(x, W, N);

    k_gather<<<(N + 7) / 8, 256>>>(N);

    k_bnstats<<<512, 128>>>(N);
    k_bnparam<<<1, DD>>>(gamma, 1.0f / (float)N);

    int n4 = N * (DD / 4);
    k_final<<<(n4 + 255) / 256, 256>>>(x, beta, out, n4);
}

// round 6
// speedup vs baseline: 2.5853x; 1.1738x over previous
#include <cuda_runtime.h>

#define NN 50000
#define EE 800000
#define DD 128
#define BN_EPS 1e-5f
#define SCAN_B 1024
#define NBLK ((NN + SCAN_B - 1) / SCAN_B)   // 49

// ---- scratch (device globals: allocation-free per harness rules) ----
__device__ float g_xw[NN * DD];      // x @ W
__device__ float g_agg[NN * DD];     // aggregated output of GCN conv
__device__ float g_dinv[NN];
__device__ int   g_degi[NN];
__device__ int   g_off[NN + 1];      // CSR offsets
__device__ int   g_cur[NN];          // fill cursors
__device__ int   g_rowi[EE];         // edge rows as int32
__device__ int   g_coli[EE];         // edge cols as int32
__device__ int   g_adj[EE];          // CSR adjacency (col indices)
__device__ int   g_bsum[NBLK];       // per-block scan totals
__device__ float g_colsum[DD];
__device__ float g_colsumsq[DD];
__device__ float g_mean[DD];
__device__ float g_scale[DD];        // gamma * rsqrt(var+eps)
__device__ int   g_is64;             // 1 if edge_index is int64, 0 if int32

// ---- K1: zero degrees + BN accums; block 0 also detects edge dtype ----
__global__ void k_init(const void* __restrict__ ei, int N) {
    __shared__ int s_bad;
    int tid = threadIdx.x;
    if (blockIdx.x == 0) {
        if (tid == 0) s_bad = 0;
        __syncthreads();
        // read first 256 entries as int64; any out-of-range => data is int32
        long long v = ((const long long*)ei)[tid];
        if (v < 0 || v >= N) atomicOr(&s_bad, 1);
        __syncthreads();
        if (tid == 0) g_is64 = s_bad ? 0 : 1;
    }
    int i = blockIdx.x * blockDim.x + tid;
    if (i < N) g_degi[i] = 0;
    if (i < DD) { g_colsum[i] = 0.0f; g_colsumsq[i] = 0.0f; }
}

// ---- K2: convert edges to int32 + histogram rows ----
__global__ void k_prep(const void* __restrict__ ei, int E, int N) {
    int e = blockIdx.x * blockDim.x + threadIdx.x;
    if (e >= E) return;
    int row, col;
    if (g_is64) {
        row = (int)((const long long*)ei)[e];
        col = (int)((const long long*)ei)[E + e];
    } else {
        row = ((const int*)ei)[e];
        col = ((const int*)ei)[E + e];
    }
    if ((unsigned)row >= (unsigned)N || (unsigned)col >= (unsigned)N) {
        g_rowi[e] = -1; g_coli[e] = 0;
        return;
    }
    g_rowi[e] = row;
    g_coli[e] = col;
    atomicAdd(&g_degi[row], 1);
}

// ---- K3: per-block inclusive scan + block totals ----
__global__ __launch_bounds__(SCAN_B) void k_scan1(int N) {
    __shared__ int warp_tot[32];
    int tid = threadIdx.x;
    int lane = tid & 31, wid = tid >> 5;
    int i = blockIdx.x * SCAN_B + tid;
    int v = (i < N) ? g_degi[i] : 0;
    int s = v;
#pragma unroll
    for (int d = 1; d < 32; d <<= 1) {
        int t = __shfl_up_sync(0xffffffffu, s, d);
        if (lane >= d) s += t;
    }
    if (lane == 31) warp_tot[wid] = s;
    __syncthreads();
    if (wid == 0) {
        int t = warp_tot[lane];
        int ws = t;
#pragma unroll
        for (int d = 1; d < 32; d <<= 1) {
            int u = __shfl_up_sync(0xffffffffu, ws, d);
            if (lane >= d) ws += u;
        }
        warp_tot[lane] = ws - t;  // exclusive warp offsets
    }
    __syncthreads();
    int incl = s + warp_tot[wid];
    if (i < N) g_off[i + 1] = incl;          // block-local inclusive
    if (tid == SCAN_B - 1) g_bsum[blockIdx.x] = incl;
}

// ---- K4: finalize offsets (add block prefix) + dinv + fill cursors ----
__global__ void k_post(int N) {
    int i = blockIdx.x * blockDim.x + threadIdx.x;
    if (i >= N) return;
    int chunk = i >> 10;                 // SCAN_B = 1024
    int boff = 0;
    for (int b = 0; b < chunk; b++) boff += g_bsum[b];   // <=48 L1-hit loads
    int incl = g_off[i + 1] + boff;      // final inclusive = off[i+1]
    g_off[i + 1] = incl;
    int deg = g_degi[i];
    g_cur[i] = incl - deg;               // = off[i] (exclusive)
    g_dinv[i] = rsqrtf((float)(deg + 1));
    if (i == 0) g_off[0] = 0;
}

// ---- K5: CSR fill ----
__global__ void k_fill(int E) {
    int e = blockIdx.x * blockDim.x + threadIdx.x;
    if (e >= E) return;
    int row = g_rowi[e];
    if (row < 0) return;
    int pos = atomicAdd(&g_cur[row], 1);
    g_adj[pos] = g_coli[e];
}

// ---- K6: xw = x @ W (warp = 8 rows x 128 cols; W L1-resident) ----
__global__ __launch_bounds__(256) void k_gemm(const float* __restrict__ x,
                                              const float* __restrict__ W,
                                              int N) {
    int lane = threadIdx.x & 31;
    int gw = (blockIdx.x * blockDim.x + threadIdx.x) >> 5;
    int r0 = gw * 8;
    if (r0 >= N) return;
    int rows = min(8, N - r0);

    const float4* W4 = (const float4*)W;
    const float4* x4 = (const float4*)x;

    float4 acc[8];
#pragma unroll
    for (int r = 0; r < 8; r++) acc[r] = make_float4(0.f, 0.f, 0.f, 0.f);

#pragma unroll 4
    for (int k4 = 0; k4 < 32; k4++) {
        float4 wv0 = W4[(k4 * 4 + 0) * 32 + lane];
        float4 wv1 = W4[(k4 * 4 + 1) * 32 + lane];
        float4 wv2 = W4[(k4 * 4 + 2) * 32 + lane];
        float4 wv3 = W4[(k4 * 4 + 3) * 32 + lane];
#pragma unroll
        for (int r = 0; r < 8; r++) {
            int row = r0 + r; if (row >= N) row = N - 1;
            float4 xv = x4[row * 32 + k4];
            acc[r].x = fmaf(xv.x, wv0.x, acc[r].x);
            acc[r].y = fmaf(xv.x, wv0.y, acc[r].y);
            acc[r].z = fmaf(xv.x, wv0.z, acc[r].z);
            acc[r].w = fmaf(xv.x, wv0.w, acc[r].w);
            acc[r].x = fmaf(xv.y, wv1.x, acc[r].x);
            acc[r].y = fmaf(xv.y, wv1.y, acc[r].y);
            acc[r].z = fmaf(xv.y, wv1.z, acc[r].z);
            acc[r].w = fmaf(xv.y, wv1.w, acc[r].w);
            acc[r].x = fmaf(xv.z, wv2.x, acc[r].x);
            acc[r].y = fmaf(xv.z, wv2.y, acc[r].y);
            acc[r].z = fmaf(xv.z, wv2.z, acc[r].z);
            acc[r].w = fmaf(xv.z, wv2.w, acc[r].w);
            acc[r].x = fmaf(xv.w, wv3.x, acc[r].x);
            acc[r].y = fmaf(xv.w, wv3.y, acc[r].y);
            acc[r].z = fmaf(xv.w, wv3.z, acc[r].z);
            acc[r].w = fmaf(xv.w, wv3.w, acc[r].w);
        }
    }

    float4* xw4 = (float4*)g_xw;
#pragma unroll
    for (int r = 0; r < 8; r++)
        if (r < rows) xw4[(r0 + r) * 32 + lane] = acc[r];
}

// ---- K7: per-node gather (NO atomics). warp = 1 node. ----
// agg[n] = dinv[n] * ( xw[n]*dinv[n] + sum_{c in adj(n)} dinv[c]*xw[c] )
__global__ __launch_bounds__(256) void k_gather(int N) {
    int lane = threadIdx.x & 31;
    int n = (blockIdx.x * blockDim.x + threadIdx.x) >> 5;
    if (n >= N) return;
    int j = g_off[n], end = g_off[n + 1];
    const float4* xw4 = (const float4*)g_xw;

    float4 acc = make_float4(0.f, 0.f, 0.f, 0.f);
    for (; j + 2 <= end; j += 2) {                // unroll-2 for MLP
        int c0 = g_adj[j], c1 = g_adj[j + 1];
        float w0 = g_dinv[c0], w1 = g_dinv[c1];
        float4 v0 = xw4[c0 * 32 + lane];
        float4 v1 = xw4[c1 * 32 + lane];
        acc.x += v0.x * w0 + v1.x * w1;
        acc.y += v0.y * w0 + v1.y * w1;
        acc.z += v0.z * w0 + v1.z * w1;
        acc.w += v0.w * w0 + v1.w * w1;
    }
    if (j < end) {
        int c0 = g_adj[j];
        float w0 = g_dinv[c0];
        float4 v0 = xw4[c0 * 32 + lane];
        acc.x += v0.x * w0; acc.y += v0.y * w0;
        acc.z += v0.z * w0; acc.w += v0.w * w0;
    }
    float dr = g_dinv[n];
    float4 sv = xw4[n * 32 + lane];
    acc.x = (acc.x + sv.x * dr) * dr;
    acc.y = (acc.y + sv.y * dr) * dr;
    acc.z = (acc.z + sv.z * dr) * dr;
    acc.w = (acc.w + sv.w * dr) * dr;
    ((float4*)g_agg)[n * 32 + lane] = acc;
}

// ---- K8: BN column statistics ----
__global__ void k_bnstats(int N) {
    int c = threadIdx.x;
    float s = 0.f, s2 = 0.f;
    for (int r = blockIdx.x; r < N; r += gridDim.x) {
        float v = g_agg[r * DD + c];
        s += v;
        s2 = fmaf(v, v, s2);
    }
    atomicAdd(&g_colsum[c], s);
    atomicAdd(&g_colsumsq[c], s2);
}

// ---- K9: finalize BN params (bias b cancels through mean subtraction) ----
__global__ void k_bnparam(const float* __restrict__ gamma, float nInv) {
    int c = threadIdx.x;
    float mean = g_colsum[c] * nInv;
    float var = g_colsumsq[c] * nInv - mean * mean;
    g_mean[c] = mean;
    g_scale[c] = rsqrtf(var + BN_EPS) * gamma[c];
}

// ---- K10: y = relu((agg - mean)*scale + beta) + x ----
__global__ void k_final(const float* __restrict__ x, const float* __restrict__ beta,
                        float* __restrict__ out, int n4) {
    int t = blockIdx.x * blockDim.x + threadIdx.x;
    if (t >= n4) return;
    int cb = t & 31;
    float4 a  = ((const float4*)g_agg)[t];
    float4 xr = ((const float4*)x)[t];
    float4 m  = ((const float4*)g_mean)[cb];
    float4 s  = ((const float4*)g_scale)[cb];
    float4 bt = ((const float4*)beta)[cb];
    float4 r;
    r.x = fmaxf((a.x - m.x) * s.x + bt.x, 0.f) + xr.x;
    r.y = fmaxf((a.y - m.y) * s.y + bt.y, 0.f) + xr.y;
    r.z = fmaxf((a.z - m.z) * s.z + bt.z, 0.f) + xr.z;
    r.w = fmaxf((a.w - m.w) * s.w + bt.w, 0.f) + xr.w;
    ((float4*)out)[t] = r;
}

extern "C" void kernel_launch(void* const* d_in, const int* in_sizes, int n_in,
                              void* d_out, int out_size) {
    const float* x     = (const float*)d_in[0];
    const void*  ei    = d_in[1];                 // int32 or int64, detected on device
    const float* W     = (const float*)d_in[2];
    // d_in[3] = b — cancels exactly through BatchNorm, unused
    const float* gamma = (const float*)d_in[4];
    const float* beta  = (const float*)d_in[5];
    float*       out   = (float*)d_out;

    int N = in_sizes[0] / DD;
    int E = in_sizes[1] / 2;
    int nblk = (N + SCAN_B - 1) / SCAN_B;

    // one-time side-stream + events (host objects only; no device memory)
    static cudaStream_t s2 = nullptr;
    static cudaEvent_t ev_fork = nullptr, ev_join = nullptr;
    if (s2 == nullptr) {
        cudaStreamCreateWithFlags(&s2, cudaStreamNonBlocking);
        cudaEventCreateWithFlags(&ev_fork, cudaEventDisableTiming);
        cudaEventCreateWithFlags(&ev_join, cudaEventDisableTiming);
    }

    // ---- fork: GEMM (x,W only) runs concurrently with the CSR build ----
    cudaEventRecord(ev_fork, 0);
    cudaStreamWaitEvent(s2, ev_fork, 0);
    int gwarps = (N + 7) / 8;
    k_gemm<<<(gwarps + 7) / 8, 256, 0, s2>>>(x, W, N);
    cudaEventRecord(ev_join, s2);

    // ---- CSR build chain on the main stream ----
    k_init<<<(N + 255) / 256, 256>>>(ei, N);
    k_prep<<<(E + 255) / 256, 256>>>(ei, E, N);
    k_scan1<<<nblk, SCAN_B>>>(N);
    k_post<<<(N + 255) / 256, 256>>>(N);
    k_fill<<<(E + 255) / 256, 256>>>(E);

    // ---- join, then aggregate ----
    cudaStreamWaitEvent(0, ev_join, 0);
    k_gather<<<(N + 7) / 8, 256>>>(N);

    k_bnstats<<<512, 128>>>(N);
    k_bnparam<<<1, DD>>>(gamma, 1.0f / (float)N);

    int n4 = N * (DD / 4);
    k_final<<<(n4 + 255) / 256, 256>>>(x, beta, out, n4);
}